// round 1
// baseline (speedup 1.0000x reference)
#include <cuda_runtime.h>

#define NG 21

struct Meta {
    const float* f[6];
    const float* w[6];
    float*       out;
    int cg_off[NG][6];
    int col_base[NG][6];
};

__device__ float d_cg[4096];

__constant__ int c_NUMCOLS[6] = {1536, 2560, 3328, 3584, 3584, 3072};
__constant__ int c_FOFF[7]    = {0, 32, 128, 288, 512, 800, 1152};
__constant__ int c_OUTOFF[6]  = {0, 8192, 32768, 73728, 131072, 204800};

// ---------------------------------------------------------------------------
// CG coefficient init (Racah formula), computed on device each launch.
// Factorials up to 16! are exactly representable in double.
// ---------------------------------------------------------------------------
__device__ double dfact(int n) {
    double r = 1.0;
    for (int i = 2; i <= n; i++) r *= (double)i;
    return r;
}

__device__ double cg_coeff_d(int l1, int l2, int l, int m1, int m2, int m) {
    double pref = sqrt((2.0 * l + 1.0) * dfact(l + l1 - l2) * dfact(l - l1 + l2) *
                       dfact(l1 + l2 - l) / dfact(l1 + l2 + l + 1));
    pref *= sqrt(dfact(l + m) * dfact(l - m) * dfact(l1 - m1) * dfact(l1 + m1) *
                 dfact(l2 - m2) * dfact(l2 + m2));
    int kmin = 0;
    if (l2 - l - m1 > kmin) kmin = l2 - l - m1;
    if (l1 + m2 - l > kmin) kmin = l1 + m2 - l;
    int kmax = l1 + l2 - l;
    if (l1 - m1 < kmax) kmax = l1 - m1;
    if (l2 + m2 < kmax) kmax = l2 + m2;
    double s = 0.0;
    for (int k = kmin; k <= kmax; k++) {
        double d = dfact(k) * dfact(l1 + l2 - l - k) * dfact(l1 - m1 - k) *
                   dfact(l2 + m2 - k) * dfact(l - l2 + m1 + k) * dfact(l - l1 - m2 + k);
        s += ((k & 1) ? -1.0 : 1.0) / d;
    }
    return pref * s;
}

__global__ void cg_init_kernel(Meta meta) {
    int tid = threadIdx.x;
    int g = 0;
    for (int l1 = 0; l1 <= 5; l1++) {
        for (int l2 = 0; l2 <= l1; l2++) {
            int lmin = l1 - l2;
            int lmax = (l1 + l2 < 5) ? (l1 + l2) : 5;
            for (int l = lmin; l <= lmax; l++) {
                int n1 = 2 * l1 + 1, n2 = 2 * l2 + 1;
                for (int idx = tid; idx < n1 * n2; idx += blockDim.x) {
                    int m1i = idx / n2, m2i = idx % n2;
                    int m1 = m1i - l1, m2 = m2i - l2, m = m1 + m2;
                    float c = 0.0f;
                    if (m >= -l && m <= l)
                        c = (float)cg_coeff_d(l1, l2, l, m1, m2, m);
                    d_cg[meta.cg_off[g][l] + idx] = c;
                }
            }
            g++;
        }
    }
}

// ---------------------------------------------------------------------------
// Main fused kernel: one CTA per batch element b.
// For each (l1,l2) group: stage1 computes CG fragments for all 256 (i,j)
// channel pairs into smem; stage2 contracts them with the weights into the
// per-b output accumulator in smem.
// ---------------------------------------------------------------------------
template <int L1, int L2>
__device__ __forceinline__ void process_group(
    int g, const Meta& meta, float* __restrict__ f_s, float* __restrict__ out_s,
    float* __restrict__ cg_s, int* __restrict__ lutA, int* __restrict__ lutB,
    float* __restrict__ frag_s, int tid)
{
    constexpr int LMIN  = L1 - L2;
    constexpr int LMAX2 = (L1 + L2 < 5) ? (L1 + L2) : 5;
    constexpr int N1 = 2 * L1 + 1;
    constexpr int N2 = 2 * L2 + 1;
    constexpr int STRIDE = N1 * N2;
    constexpr int NL = LMAX2 - LMIN + 1;
    constexpr int SK = (LMAX2 + 1) * (LMAX2 + 1) - LMIN * LMIN;  // sum of (2l+1)
    constexpr int E = 16 * SK;

    __syncthreads();  // prior group's stage2 done with cg/lut/frag

    // copy this group's CG block (contiguous across its l range)
    {
        const float* src = d_cg + meta.cg_off[g][LMIN];
        for (int s = tid; s < NL * STRIDE; s += 256) cg_s[s] = src[s];
    }
    // build (l,t,k) work list
    for (int e = tid; e < E; e += 256) {
        int t = e & 15, kk = e >> 4;
        int l = LMIN;
#pragma unroll
        for (int ll = LMIN; ll < LMAX2; ll++)
            if (kk >= (ll + 1) * (ll + 1) - LMIN * LMIN) l = ll + 1;
        int k = kk - (l * l - LMIN * LMIN);
        int woff = (t * c_NUMCOLS[l] + meta.col_base[g][l]) * 2;
        lutA[e] = (l << 27) | woff;
        lutB[e] = (kk << 16) | (c_FOFF[l] + (t * (2 * l + 1) + k) * 2);
    }
    __syncthreads();  // cg + lut ready (and f_s on the first group)

    // ---- stage 1: CG fragments, thread = (i,j) channel pair = column ----
    {
        int i = tid >> 4, j = tid & 15;
        float accr[SK], acci[SK];
#pragma unroll
        for (int q = 0; q < SK; q++) { accr[q] = 0.0f; acci[q] = 0.0f; }
        const float* f1 = f_s + c_FOFF[L1] + i * N1 * 2;
        const float* f2 = f_s + c_FOFF[L2] + j * N2 * 2;
#pragma unroll
        for (int m1 = 0; m1 < N1; m1++) {
            float ar = f1[2 * m1], ai = f1[2 * m1 + 1];
#pragma unroll
            for (int m2 = 0; m2 < N2; m2++) {
                float br = f2[2 * m2], bi = f2[2 * m2 + 1];
                float pr = ar * br - ai * bi;
                float pi = ar * bi + ai * br;
                int m = m1 + m2 - L1 - L2;
#pragma unroll
                for (int l = LMIN; l <= LMAX2; l++) {
                    if (m >= -l && m <= l) {
                        float c = cg_s[(l - LMIN) * STRIDE + m1 * N2 + m2];
                        int kk = (l * l - LMIN * LMIN) + m + l;
                        accr[kk] += c * pr;
                        acci[kk] += c * pi;
                    }
                }
            }
        }
#pragma unroll
        for (int q = 0; q < SK; q++) {
            frag_s[(q * 256 + tid) * 2]     = accr[q];
            frag_s[(q * 256 + tid) * 2 + 1] = acci[q];
        }
    }
    __syncthreads();  // fragments ready

    // ---- stage 2: weight contraction over ij for each (l,t,k) ----
    for (int e = tid; e < E; e += 256) {
        int a = lutA[e];
        int l = a >> 27;
        int woff = a & ((1 << 27) - 1);
        int bdat = lutB[e];
        int kk = bdat >> 16;
        int ooff = bdat & 0xffff;
        const float4* wp = (const float4*)(meta.w[l] + woff);
        const float4* fp = (const float4*)(frag_s + kk * 512);
        float sr = 0.0f, si = 0.0f;
#pragma unroll 4
        for (int q = 0; q < 128; q++) {
            float4 w4 = __ldg(wp + q);
            float4 f4 = fp[q];
            sr += w4.x * f4.x - w4.y * f4.y;
            si += w4.x * f4.y + w4.y * f4.x;
            sr += w4.z * f4.z - w4.w * f4.w;
            si += w4.z * f4.w + w4.w * f4.z;
        }
        out_s[ooff]     += sr;
        out_s[ooff + 1] += si;
    }
}

__global__ void __launch_bounds__(256, 1) uf_kernel(Meta meta) {
    extern __shared__ float smem[];
    float* f_s    = smem;                       // 1152 floats
    float* out_s  = smem + 1152;                // 1152
    float* cg_s   = smem + 2304;                // 732
    int*   lutA   = (int*)(smem + 3036);        // 576
    int*   lutB   = lutA + 576;                 // 576
    float* frag_s = smem + 4188;                // 18432 (16B-aligned)

    int tid = threadIdx.x;
    int b = blockIdx.x;

    // load this batch element's f into smem; zero the output accumulator
#pragma unroll
    for (int l = 0; l < 6; l++) {
        int n = 32 * (2 * l + 1);
        const float* src = meta.f[l] + b * n;
        for (int s = tid; s < n; s += 256) f_s[c_FOFF[l] + s] = src[s];
    }
    for (int s = tid; s < 1152; s += 256) out_s[s] = 0.0f;

#define PG(A, B2, G) process_group<A, B2>(G, meta, f_s, out_s, cg_s, lutA, lutB, frag_s, tid)
    PG(0, 0, 0);
    PG(1, 0, 1);  PG(1, 1, 2);
    PG(2, 0, 3);  PG(2, 1, 4);  PG(2, 2, 5);
    PG(3, 0, 6);  PG(3, 1, 7);  PG(3, 2, 8);  PG(3, 3, 9);
    PG(4, 0, 10); PG(4, 1, 11); PG(4, 2, 12); PG(4, 3, 13); PG(4, 4, 14);
    PG(5, 0, 15); PG(5, 1, 16); PG(5, 2, 17); PG(5, 3, 18); PG(5, 4, 19); PG(5, 5, 20);
#undef PG

    __syncthreads();
    // write out: per-l layout [B, 16, 2l+1, 2], outputs concatenated l=0..5
    for (int s = tid; s < 1152; s += 256) {
        int l = 0;
#pragma unroll
        for (int ll = 1; ll < 6; ll++)
            if (s >= c_FOFF[ll]) l = ll;
        int rel = s - c_FOFF[l];
        meta.out[c_OUTOFF[l] + b * 32 * (2 * l + 1) + rel] = out_s[s];
    }
}

// ---------------------------------------------------------------------------
// Host launch
// ---------------------------------------------------------------------------
extern "C" void kernel_launch(void* const* d_in, const int* in_sizes, int n_in,
                              void* d_out, int out_size) {
    Meta m;
    // identify inputs by element count (f sizes unique; w3/w4 tie broken by order)
    const int fsz[6] = {8192, 24576, 40960, 57344, 73728, 90112};
    const int wsz[6] = {49152, 81920, 106496, 114688, 114688, 98304};
    bool used[64];
    for (int i = 0; i < 64; i++) used[i] = false;
    for (int l = 0; l < 6; l++) {
        for (int idx = 0; idx < n_in; idx++) {
            if (!used[idx] && in_sizes[idx] == fsz[l]) {
                m.f[l] = (const float*)d_in[idx];
                used[idx] = true;
                break;
            }
        }
    }
    for (int l = 0; l < 6; l++) {
        for (int idx = 0; idx < n_in; idx++) {
            if (!used[idx] && in_sizes[idx] == wsz[l]) {
                m.w[l] = (const float*)d_in[idx];
                used[idx] = true;
                break;
            }
        }
    }
    m.out = (float*)d_out;

    // triple enumeration (matches reference _build_cg order)
    int off = 0, g = 0;
    int cnt[6] = {0, 0, 0, 0, 0, 0};
    for (int l1 = 0; l1 <= 5; l1++) {
        for (int l2 = 0; l2 <= l1; l2++) {
            int lmin = l1 - l2;
            int lmax = (l1 + l2 < 5) ? (l1 + l2) : 5;
            for (int l = lmin; l <= lmax; l++) {
                m.cg_off[g][l] = off;
                off += (2 * l1 + 1) * (2 * l2 + 1);
                m.col_base[g][l] = cnt[l] * 256;
                cnt[l]++;
            }
            g++;
        }
    }

    const int SMEM_BYTES = (4188 + 18432) * 4;  // 90480
    cudaFuncSetAttribute(uf_kernel, cudaFuncAttributeMaxDynamicSharedMemorySize, SMEM_BYTES);

    cg_init_kernel<<<1, 256>>>(m);
    uf_kernel<<<256, 256, SMEM_BYTES>>>(m);
}

// round 2
// speedup vs baseline: 2.0529x; 2.0529x over previous
#include <cuda_runtime.h>

#define NG 21

struct Meta {
    const float* f[6];
    const float* w[6];
    float*       out;
    int cg_off[NG][6];
    int col_base[NG][6];
};

__device__ float d_cg[4096];
__device__ float d_wt[565248];   // transposed weights, all l concatenated

__constant__ int c_NUMCOLS[6] = {1536, 2560, 3328, 3584, 3584, 3072};
__constant__ int c_FOFF[7]    = {0, 32, 128, 288, 512, 800, 1152};
__constant__ int c_OUTOFF[6]  = {0, 8192, 32768, 73728, 131072, 204800};
__constant__ int c_WTOFF[6]   = {0, 49152, 131072, 237568, 352256, 466944};

// ---------------------------------------------------------------------------
// CG coefficient init (Racah formula), computed on device each launch.
// ---------------------------------------------------------------------------
__device__ double dfact(int n) {
    double r = 1.0;
    for (int i = 2; i <= n; i++) r *= (double)i;
    return r;
}

__device__ double cg_coeff_d(int l1, int l2, int l, int m1, int m2, int m) {
    double pref = sqrt((2.0 * l + 1.0) * dfact(l + l1 - l2) * dfact(l - l1 + l2) *
                       dfact(l1 + l2 - l) / dfact(l1 + l2 + l + 1));
    pref *= sqrt(dfact(l + m) * dfact(l - m) * dfact(l1 - m1) * dfact(l1 + m1) *
                 dfact(l2 - m2) * dfact(l2 + m2));
    int kmin = 0;
    if (l2 - l - m1 > kmin) kmin = l2 - l - m1;
    if (l1 + m2 - l > kmin) kmin = l1 + m2 - l;
    int kmax = l1 + l2 - l;
    if (l1 - m1 < kmax) kmax = l1 - m1;
    if (l2 + m2 < kmax) kmax = l2 + m2;
    double s = 0.0;
    for (int k = kmin; k <= kmax; k++) {
        double d = dfact(k) * dfact(l1 + l2 - l - k) * dfact(l1 - m1 - k) *
                   dfact(l2 + m2 - k) * dfact(l - l2 + m1 + k) * dfact(l - l1 - m2 + k);
        s += ((k & 1) ? -1.0 : 1.0) / d;
    }
    return pref * s;
}

__global__ void cg_init_kernel(Meta meta) {
    int tid = threadIdx.x;
    int g = 0;
    for (int l1 = 0; l1 <= 5; l1++) {
        for (int l2 = 0; l2 <= l1; l2++) {
            int lmin = l1 - l2;
            int lmax = (l1 + l2 < 5) ? (l1 + l2) : 5;
            for (int l = lmin; l <= lmax; l++) {
                int n1 = 2 * l1 + 1, n2 = 2 * l2 + 1;
                for (int idx = tid; idx < n1 * n2; idx += blockDim.x) {
                    int m1i = idx / n2, m2i = idx % n2;
                    int m1 = m1i - l1, m2 = m2i - l2, m = m1 + m2;
                    float c = 0.0f;
                    if (m >= -l && m <= l)
                        c = (float)cg_coeff_d(l1, l2, l, m1, m2, m);
                    d_cg[meta.cg_off[g][l] + idx] = c;
                }
            }
            g++;
        }
    }
}

// ---------------------------------------------------------------------------
// Weight transpose: w[l][t][c][2] -> wt[l][c/2][t][4] where the float4 holds
// {re(c0), im(c0), re(c1), im(c1)} for channel pair (c0=2p, c1=2p+1), thread t.
// Dest-major mapping for coalesced stores.
// ---------------------------------------------------------------------------
__global__ void wt_kernel(Meta m) {
    int j = blockIdx.x * blockDim.x + threadIdx.x;
    if (j >= 565248) return;
    int l = 0;
#pragma unroll
    for (int ll = 1; ll < 6; ll++)
        if (j >= c_WTOFF[ll]) l = ll;
    int r = j - c_WTOFF[l];
    int q = r & 3;
    int pt = r >> 2;
    int t = pt & 15;
    int p = pt >> 4;
    int c = 2 * p + (q >> 1);
    int ri = q & 1;
    d_wt[j] = m.w[l][(t * c_NUMCOLS[l] + c) * 2 + ri];
}

// ---------------------------------------------------------------------------
// Main fused kernel: one CTA per batch element. Each (l1,l2) group is split
// into l-subranges [LA,LB] with SK <= 21 to bound registers and frag smem.
// ---------------------------------------------------------------------------
template <int L1, int L2, int LA, int LB>
__device__ __forceinline__ void process_range(
    int g, const Meta& meta, float* __restrict__ f_s, float* __restrict__ out_s,
    float* __restrict__ cg_s, int* __restrict__ lutA, int* __restrict__ lutB,
    float* __restrict__ frag_s, int tid)
{
    constexpr int N1 = 2 * L1 + 1;
    constexpr int N2 = 2 * L2 + 1;
    constexpr int STRIDE = N1 * N2;
    constexpr int NL = LB - LA + 1;
    constexpr int SK = (LB + 1) * (LB + 1) - LA * LA;  // sum of (2l+1), l=LA..LB
    constexpr int E = 16 * SK;

    __syncthreads();  // prior phase done with cg/lut/frag

    // copy this subrange's CG block (contiguous across its l range)
    {
        const float* src = d_cg + meta.cg_off[g][LA];
        for (int s = tid; s < NL * STRIDE; s += 256) cg_s[s] = src[s];
    }
    // build (l,t,k) work list
    for (int e = tid; e < E; e += 256) {
        int t = e & 15, kk = e >> 4;
        int l = LA;
#pragma unroll
        for (int ll = LA; ll < LB; ll++)
            if (kk >= (ll + 1) * (ll + 1) - LA * LA) l = ll + 1;
        int k = kk - (l * l - LA * LA);
        // transposed-weight base for (l, t) at this group's column block
        lutA[e] = c_WTOFF[l] + (meta.col_base[g][l] >> 1) * 64 + t * 4;
        lutB[e] = (kk << 16) | (c_FOFF[l] + (t * (2 * l + 1) + k) * 2);
    }
    __syncthreads();  // cg + lut ready

    // ---- stage 1: CG fragments, thread = (i,j) channel pair = column ----
    {
        int i = tid >> 4, j = tid & 15;
        float accr[SK], acci[SK];
#pragma unroll
        for (int q = 0; q < SK; q++) { accr[q] = 0.0f; acci[q] = 0.0f; }
        const float* f1 = f_s + c_FOFF[L1] + i * N1 * 2;
        const float* f2 = f_s + c_FOFF[L2] + j * N2 * 2;
#pragma unroll
        for (int m1 = 0; m1 < N1; m1++) {
            float ar = f1[2 * m1], ai = f1[2 * m1 + 1];
#pragma unroll
            for (int m2 = 0; m2 < N2; m2++) {
                float br = f2[2 * m2], bi = f2[2 * m2 + 1];
                float pr = ar * br - ai * bi;
                float pi = ar * bi + ai * br;
                int m = m1 + m2 - L1 - L2;
#pragma unroll
                for (int l = LA; l <= LB; l++) {
                    if (m >= -l && m <= l) {
                        float c = cg_s[(l - LA) * STRIDE + m1 * N2 + m2];
                        int kk = (l * l - LA * LA) + m + l;
                        accr[kk] += c * pr;
                        acci[kk] += c * pi;
                    }
                }
            }
        }
#pragma unroll
        for (int q = 0; q < SK; q++) {
            frag_s[(q * 256 + tid) * 2]     = accr[q];
            frag_s[(q * 256 + tid) * 2 + 1] = acci[q];
        }
    }
    __syncthreads();  // fragments ready

    // ---- stage 2: weight contraction; lanes t=0..15 consecutive => coalesced
    for (int e = tid; e < E; e += 256) {
        const float4* wp = (const float4*)(d_wt + lutA[e]);
        int bd = lutB[e];
        const float4* fp = (const float4*)(frag_s + (bd >> 16) * 512);
        float sr = 0.0f, si = 0.0f;
#pragma unroll 8
        for (int p = 0; p < 128; p++) {
            float4 w4 = wp[p * 16];   // stride 64 floats = 16 threads * float4
            float4 f4 = fp[p];
            sr += w4.x * f4.x - w4.y * f4.y;
            si += w4.x * f4.y + w4.y * f4.x;
            sr += w4.z * f4.z - w4.w * f4.w;
            si += w4.z * f4.w + w4.w * f4.z;
        }
        int ooff = bd & 0xffff;
        out_s[ooff]     += sr;
        out_s[ooff + 1] += si;
    }
}

__global__ void __launch_bounds__(256, 2) uf_kernel(Meta meta) {
    extern __shared__ float smem[];
    float* f_s    = smem;                 // 1152 floats
    float* out_s  = smem + 1152;          // 1152
    float* cg_s   = smem + 2304;          // 512 (max 484 used)
    int*   lutA   = (int*)(smem + 2816);  // 352
    int*   lutB   = lutA + 352;           // 352
    float* frag_s = smem + 3520;          // 10752 (21 rows * 512), 16B-aligned

    int tid = threadIdx.x;
    int b = blockIdx.x;

#pragma unroll
    for (int l = 0; l < 6; l++) {
        int n = 32 * (2 * l + 1);
        const float* src = meta.f[l] + b * n;
        for (int s = tid; s < n; s += 256) f_s[c_FOFF[l] + s] = src[s];
    }
    for (int s = tid; s < 1152; s += 256) out_s[s] = 0.0f;

#define PG(A, B2, G, LA, LB) \
    process_range<A, B2, LA, LB>(G, meta, f_s, out_s, cg_s, lutA, lutB, frag_s, tid)
    PG(0, 0, 0, 0, 0);
    PG(1, 0, 1, 1, 1);
    PG(1, 1, 2, 0, 2);
    PG(2, 0, 3, 2, 2);
    PG(2, 1, 4, 1, 3);
    PG(2, 2, 5, 0, 3);  PG(2, 2, 5, 4, 4);
    PG(3, 0, 6, 3, 3);
    PG(3, 1, 7, 2, 4);
    PG(3, 2, 8, 1, 3);  PG(3, 2, 8, 4, 5);
    PG(3, 3, 9, 0, 3);  PG(3, 3, 9, 4, 5);
    PG(4, 0, 10, 4, 4);
    PG(4, 1, 11, 3, 4); PG(4, 1, 11, 5, 5);
    PG(4, 2, 12, 2, 4); PG(4, 2, 12, 5, 5);
    PG(4, 3, 13, 1, 3); PG(4, 3, 13, 4, 5);
    PG(4, 4, 14, 0, 3); PG(4, 4, 14, 4, 5);
    PG(5, 0, 15, 5, 5);
    PG(5, 1, 16, 4, 5);
    PG(5, 2, 17, 3, 4); PG(5, 2, 17, 5, 5);
    PG(5, 3, 18, 2, 4); PG(5, 3, 18, 5, 5);
    PG(5, 4, 19, 1, 3); PG(5, 4, 19, 4, 5);
    PG(5, 5, 20, 0, 3); PG(5, 5, 20, 4, 5);
#undef PG

    __syncthreads();
    // write out: per-l layout [B, 16, 2l+1, 2], outputs concatenated l=0..5
    for (int s = tid; s < 1152; s += 256) {
        int l = 0;
#pragma unroll
        for (int ll = 1; ll < 6; ll++)
            if (s >= c_FOFF[ll]) l = ll;
        int rel = s - c_FOFF[l];
        meta.out[c_OUTOFF[l] + b * 32 * (2 * l + 1) + rel] = out_s[s];
    }
}

// ---------------------------------------------------------------------------
// Host launch
// ---------------------------------------------------------------------------
extern "C" void kernel_launch(void* const* d_in, const int* in_sizes, int n_in,
                              void* d_out, int out_size) {
    Meta m;
    const int fsz[6] = {8192, 24576, 40960, 57344, 73728, 90112};
    const int wsz[6] = {49152, 81920, 106496, 114688, 114688, 98304};
    bool used[64];
    for (int i = 0; i < 64; i++) used[i] = false;
    for (int l = 0; l < 6; l++) {
        for (int idx = 0; idx < n_in; idx++) {
            if (!used[idx] && in_sizes[idx] == fsz[l]) {
                m.f[l] = (const float*)d_in[idx];
                used[idx] = true;
                break;
            }
        }
    }
    for (int l = 0; l < 6; l++) {
        for (int idx = 0; idx < n_in; idx++) {
            if (!used[idx] && in_sizes[idx] == wsz[l]) {
                m.w[l] = (const float*)d_in[idx];
                used[idx] = true;
                break;
            }
        }
    }
    m.out = (float*)d_out;

    int off = 0, g = 0;
    int cnt[6] = {0, 0, 0, 0, 0, 0};
    for (int l1 = 0; l1 <= 5; l1++) {
        for (int l2 = 0; l2 <= l1; l2++) {
            int lmin = l1 - l2;
            int lmax = (l1 + l2 < 5) ? (l1 + l2) : 5;
            for (int l = lmin; l <= lmax; l++) {
                m.cg_off[g][l] = off;
                off += (2 * l1 + 1) * (2 * l2 + 1);
                m.col_base[g][l] = cnt[l] * 256;
                cnt[l]++;
            }
            g++;
        }
    }

    const int SMEM_BYTES = (3520 + 10752) * 4;  // 57088
    cudaFuncSetAttribute(uf_kernel, cudaFuncAttributeMaxDynamicSharedMemorySize, SMEM_BYTES);

    cg_init_kernel<<<1, 256>>>(m);
    wt_kernel<<<(565248 + 1023) / 1024, 1024>>>(m);
    uf_kernel<<<256, 256, SMEM_BYTES>>>(m);
}

// round 3
// speedup vs baseline: 5.4116x; 2.6361x over previous
#include <cuda_runtime.h>

#define NG 21
#define NTRIP 69

struct Meta {
    const float* f[6];
    const float* w[6];
    float*       out;
    int cg_off[NG][6];
    int col_base[NG][6];
    int trip_l1[NTRIP];
    int trip_l2[NTRIP];
    int trip_l[NTRIP];
    int trip_off[NTRIP];
};

__device__ float d_cg[4096];
__device__ float d_wt[565248];   // transposed weights, all l concatenated

__constant__ int c_NUMCOLS[6] = {1536, 2560, 3328, 3584, 3584, 3072};
__constant__ int c_FOFF[7]    = {0, 32, 128, 288, 512, 800, 1152};
__constant__ int c_OUTOFF[6]  = {0, 8192, 32768, 73728, 131072, 204800};
__constant__ int c_WTOFF[6]   = {0, 49152, 131072, 237568, 352256, 466944};

// Exact factorials 0!..16! (all exactly representable in double)
__constant__ double c_fact[17] = {
    1.0, 1.0, 2.0, 6.0, 24.0, 120.0, 720.0, 5040.0, 40320.0, 362880.0,
    3628800.0, 39916800.0, 479001600.0, 6227020800.0, 87178291200.0,
    1307674368000.0, 20922789888000.0
};

// ---------------------------------------------------------------------------
// CG coefficient init (Racah formula). One CTA per (l1,l2,l) triple, one
// coefficient per thread; factorials from constant table (no FP64 chains).
// ---------------------------------------------------------------------------
__device__ double cg_coeff_d(int l1, int l2, int l, int m1, int m2, int m) {
    double pref = sqrt((2.0 * l + 1.0) * c_fact[l + l1 - l2] * c_fact[l - l1 + l2] *
                       c_fact[l1 + l2 - l] / c_fact[l1 + l2 + l + 1]);
    pref *= sqrt(c_fact[l + m] * c_fact[l - m] * c_fact[l1 - m1] * c_fact[l1 + m1] *
                 c_fact[l2 - m2] * c_fact[l2 + m2]);
    int kmin = 0;
    if (l2 - l - m1 > kmin) kmin = l2 - l - m1;
    if (l1 + m2 - l > kmin) kmin = l1 + m2 - l;
    int kmax = l1 + l2 - l;
    if (l1 - m1 < kmax) kmax = l1 - m1;
    if (l2 + m2 < kmax) kmax = l2 + m2;
    double s = 0.0;
    for (int k = kmin; k <= kmax; k++) {
        double d = c_fact[k] * c_fact[l1 + l2 - l - k] * c_fact[l1 - m1 - k] *
                   c_fact[l2 + m2 - k] * c_fact[l - l2 + m1 + k] * c_fact[l - l1 - m2 + k];
        s += ((k & 1) ? -1.0 : 1.0) / d;
    }
    return pref * s;
}

__global__ void cg_init_kernel(Meta meta) {
    int tr = blockIdx.x;
    int l1 = meta.trip_l1[tr], l2 = meta.trip_l2[tr], l = meta.trip_l[tr];
    int off = meta.trip_off[tr];
    int n1 = 2 * l1 + 1, n2 = 2 * l2 + 1;
    int idx = threadIdx.x;
    if (idx >= n1 * n2) return;
    int m1i = idx / n2, m2i = idx % n2;
    int m1 = m1i - l1, m2 = m2i - l2, m = m1 + m2;
    float c = 0.0f;
    if (m >= -l && m <= l)
        c = (float)cg_coeff_d(l1, l2, l, m1, m2, m);
    d_cg[off + idx] = c;
}

// ---------------------------------------------------------------------------
// Weight transpose: w[l][t][c][2] -> wt[l][c/2][t][4] where the float4 holds
// {re(c0), im(c0), re(c1), im(c1)} for channel pair (c0=2p, c1=2p+1), thread t.
// ---------------------------------------------------------------------------
__global__ void wt_kernel(Meta m) {
    int j = blockIdx.x * blockDim.x + threadIdx.x;
    if (j >= 565248) return;
    int l = 0;
#pragma unroll
    for (int ll = 1; ll < 6; ll++)
        if (j >= c_WTOFF[ll]) l = ll;
    int r = j - c_WTOFF[l];
    int q = r & 3;
    int pt = r >> 2;
    int t = pt & 15;
    int p = pt >> 4;
    int c = 2 * p + (q >> 1);
    int ri = q & 1;
    d_wt[j] = m.w[l][(t * c_NUMCOLS[l] + c) * 2 + ri];
}

// ---------------------------------------------------------------------------
// Main fused kernel: one CTA per batch element. Each (l1,l2) group is split
// into l-subranges [LA,LB] with SK <= 21 to bound registers and frag smem.
// ---------------------------------------------------------------------------
template <int L1, int L2, int LA, int LB>
__device__ __forceinline__ void process_range(
    int g, const Meta& meta, float* __restrict__ f_s, float* __restrict__ out_s,
    float* __restrict__ cg_s, int* __restrict__ lutA, int* __restrict__ lutB,
    float* __restrict__ frag_s, int tid)
{
    constexpr int N1 = 2 * L1 + 1;
    constexpr int N2 = 2 * L2 + 1;
    constexpr int STRIDE = N1 * N2;
    constexpr int NL = LB - LA + 1;
    constexpr int SK = (LB + 1) * (LB + 1) - LA * LA;  // sum of (2l+1), l=LA..LB
    constexpr int E = 16 * SK;

    __syncthreads();  // prior phase done with cg/lut/frag

    // copy this subrange's CG block (contiguous across its l range)
    {
        const float* src = d_cg + meta.cg_off[g][LA];
        for (int s = tid; s < NL * STRIDE; s += 256) cg_s[s] = src[s];
    }
    // build (l,t,k) work list
    for (int e = tid; e < E; e += 256) {
        int t = e & 15, kk = e >> 4;
        int l = LA;
#pragma unroll
        for (int ll = LA; ll < LB; ll++)
            if (kk >= (ll + 1) * (ll + 1) - LA * LA) l = ll + 1;
        int k = kk - (l * l - LA * LA);
        lutA[e] = c_WTOFF[l] + (meta.col_base[g][l] >> 1) * 64 + t * 4;
        lutB[e] = (kk << 16) | (c_FOFF[l] + (t * (2 * l + 1) + k) * 2);
    }
    __syncthreads();  // cg + lut ready

    // ---- stage 1: CG fragments, thread = (i,j) channel pair = column ----
    {
        int i = tid >> 4, j = tid & 15;
        float accr[SK], acci[SK];
#pragma unroll
        for (int q = 0; q < SK; q++) { accr[q] = 0.0f; acci[q] = 0.0f; }
        const float* f1 = f_s + c_FOFF[L1] + i * N1 * 2;
        const float* f2 = f_s + c_FOFF[L2] + j * N2 * 2;
#pragma unroll
        for (int m1 = 0; m1 < N1; m1++) {
            float ar = f1[2 * m1], ai = f1[2 * m1 + 1];
#pragma unroll
            for (int m2 = 0; m2 < N2; m2++) {
                float br = f2[2 * m2], bi = f2[2 * m2 + 1];
                float pr = ar * br - ai * bi;
                float pi = ar * bi + ai * br;
                int m = m1 + m2 - L1 - L2;
#pragma unroll
                for (int l = LA; l <= LB; l++) {
                    if (m >= -l && m <= l) {
                        float c = cg_s[(l - LA) * STRIDE + m1 * N2 + m2];
                        int kk = (l * l - LA * LA) + m + l;
                        accr[kk] += c * pr;
                        acci[kk] += c * pi;
                    }
                }
            }
        }
#pragma unroll
        for (int q = 0; q < SK; q++) {
            frag_s[(q * 256 + tid) * 2]     = accr[q];
            frag_s[(q * 256 + tid) * 2 + 1] = acci[q];
        }
    }
    __syncthreads();  // fragments ready

    // ---- stage 2: weight contraction; lanes t=0..15 consecutive => coalesced
    for (int e = tid; e < E; e += 256) {
        const float4* wp = (const float4*)(d_wt + lutA[e]);
        int bd = lutB[e];
        const float4* fp = (const float4*)(frag_s + (bd >> 16) * 512);
        float sr = 0.0f, si = 0.0f;
#pragma unroll 8
        for (int p = 0; p < 128; p++) {
            float4 w4 = wp[p * 16];   // stride 64 floats = 16 threads * float4
            float4 f4 = fp[p];
            sr += w4.x * f4.x - w4.y * f4.y;
            si += w4.x * f4.y + w4.y * f4.x;
            sr += w4.z * f4.z - w4.w * f4.w;
            si += w4.z * f4.w + w4.w * f4.z;
        }
        int ooff = bd & 0xffff;
        out_s[ooff]     += sr;
        out_s[ooff + 1] += si;
    }
}

__global__ void __launch_bounds__(256, 2) uf_kernel(Meta meta) {
    extern __shared__ float smem[];
    float* f_s    = smem;                 // 1152 floats
    float* out_s  = smem + 1152;          // 1152
    float* cg_s   = smem + 2304;          // 512 (max 484 used)
    int*   lutA   = (int*)(smem + 2816);  // 352
    int*   lutB   = lutA + 352;           // 352
    float* frag_s = smem + 3520;          // 10752 (21 rows * 512), 16B-aligned

    int tid = threadIdx.x;
    int b = blockIdx.x;

#pragma unroll
    for (int l = 0; l < 6; l++) {
        int n = 32 * (2 * l + 1);
        const float* src = meta.f[l] + b * n;
        for (int s = tid; s < n; s += 256) f_s[c_FOFF[l] + s] = src[s];
    }
    for (int s = tid; s < 1152; s += 256) out_s[s] = 0.0f;

#define PG(A, B2, G, LA, LB) \
    process_range<A, B2, LA, LB>(G, meta, f_s, out_s, cg_s, lutA, lutB, frag_s, tid)
    PG(0, 0, 0, 0, 0);
    PG(1, 0, 1, 1, 1);
    PG(1, 1, 2, 0, 2);
    PG(2, 0, 3, 2, 2);
    PG(2, 1, 4, 1, 3);
    PG(2, 2, 5, 0, 3);  PG(2, 2, 5, 4, 4);
    PG(3, 0, 6, 3, 3);
    PG(3, 1, 7, 2, 4);
    PG(3, 2, 8, 1, 3);  PG(3, 2, 8, 4, 5);
    PG(3, 3, 9, 0, 3);  PG(3, 3, 9, 4, 5);
    PG(4, 0, 10, 4, 4);
    PG(4, 1, 11, 3, 4); PG(4, 1, 11, 5, 5);
    PG(4, 2, 12, 2, 4); PG(4, 2, 12, 5, 5);
    PG(4, 3, 13, 1, 3); PG(4, 3, 13, 4, 5);
    PG(4, 4, 14, 0, 3); PG(4, 4, 14, 4, 5);
    PG(5, 0, 15, 5, 5);
    PG(5, 1, 16, 4, 5);
    PG(5, 2, 17, 3, 4); PG(5, 2, 17, 5, 5);
    PG(5, 3, 18, 2, 4); PG(5, 3, 18, 5, 5);
    PG(5, 4, 19, 1, 3); PG(5, 4, 19, 4, 5);
    PG(5, 5, 20, 0, 3); PG(5, 5, 20, 4, 5);
#undef PG

    __syncthreads();
    // write out: per-l layout [B, 16, 2l+1, 2], outputs concatenated l=0..5
    for (int s = tid; s < 1152; s += 256) {
        int l = 0;
#pragma unroll
        for (int ll = 1; ll < 6; ll++)
            if (s >= c_FOFF[ll]) l = ll;
        int rel = s - c_FOFF[l];
        meta.out[c_OUTOFF[l] + b * 32 * (2 * l + 1) + rel] = out_s[s];
    }
}

// ---------------------------------------------------------------------------
// Host launch
// ---------------------------------------------------------------------------
extern "C" void kernel_launch(void* const* d_in, const int* in_sizes, int n_in,
                              void* d_out, int out_size) {
    Meta m;
    const int fsz[6] = {8192, 24576, 40960, 57344, 73728, 90112};
    const int wsz[6] = {49152, 81920, 106496, 114688, 114688, 98304};
    bool used[64];
    for (int i = 0; i < 64; i++) used[i] = false;
    for (int l = 0; l < 6; l++) {
        for (int idx = 0; idx < n_in; idx++) {
            if (!used[idx] && in_sizes[idx] == fsz[l]) {
                m.f[l] = (const float*)d_in[idx];
                used[idx] = true;
                break;
            }
        }
    }
    for (int l = 0; l < 6; l++) {
        for (int idx = 0; idx < n_in; idx++) {
            if (!used[idx] && in_sizes[idx] == wsz[l]) {
                m.w[l] = (const float*)d_in[idx];
                used[idx] = true;
                break;
            }
        }
    }
    m.out = (float*)d_out;

    int off = 0, g = 0, tr = 0;
    int cnt[6] = {0, 0, 0, 0, 0, 0};
    for (int l1 = 0; l1 <= 5; l1++) {
        for (int l2 = 0; l2 <= l1; l2++) {
            int lmin = l1 - l2;
            int lmax = (l1 + l2 < 5) ? (l1 + l2) : 5;
            for (int l = lmin; l <= lmax; l++) {
                m.cg_off[g][l] = off;
                m.trip_l1[tr] = l1;
                m.trip_l2[tr] = l2;
                m.trip_l[tr]  = l;
                m.trip_off[tr] = off;
                tr++;
                off += (2 * l1 + 1) * (2 * l2 + 1);
                m.col_base[g][l] = cnt[l] * 256;
                cnt[l]++;
            }
            g++;
        }
    }

    const int SMEM_BYTES = (3520 + 10752) * 4;  // 57088
    cudaFuncSetAttribute(uf_kernel, cudaFuncAttributeMaxDynamicSharedMemorySize, SMEM_BYTES);

    cg_init_kernel<<<NTRIP, 128>>>(m);
    wt_kernel<<<(565248 + 1023) / 1024, 1024>>>(m);
    uf_kernel<<<256, 256, SMEM_BYTES>>>(m);
}